// round 10
// baseline (speedup 1.0000x reference)
#include <cuda_runtime.h>
#include <math_constants.h>

// Problem constants
#define NPTS   100000
#define BATCH  4096
#define TOPK   10

// Shell: points with |p|^2 >= WCUT. WCUT targets a ~2000-point shell for the
// benchmark distribution (p ~ 0.1*N(0,I)). WCUT/SMAXN only affect SPEED:
// correctness is guarded by the per-ray radius proof and the overflow path.
// SMAXN is 8.5x the nominal shell size so shell_ok cannot trip on modest
// distribution surprises (the suspected cause of R9's all-defer regression).
#define WCUT   0.0992f
#define SMAXN  16384
#define FWARPS 8

// ---------------------------------------------------------------------------
// Device scratch (static; no runtime allocation)
// ---------------------------------------------------------------------------
__device__ float4 g_shell[SMAXN];     // (x, y, z, |p|^2), unordered
__device__ int    g_sidx[SMAXN];      // original point index
__device__ int    g_ns;               // shell count (logical; may exceed SMAXN)
__device__ int    g_over_cnt;         // deferred ray count
__device__ int    g_over_ray[BATCH];
__device__ float  g_over_tau[BATCH];

// ---------------------------------------------------------------------------
// Helpers
// ---------------------------------------------------------------------------
__device__ __forceinline__ float bump_up(float x) {
    unsigned u = __float_as_uint(x);
    if (x > 0.0f)      { u += 8; }
    else if (x < 0.0f) { if ((u & 0x7FFFFFFFu) <= 8u) return 1e-30f; u -= 8; }
    else               { return 1e-30f; }
    return __uint_as_float(u);
}

__device__ __forceinline__ void ray_center(const float* ro, const float* rd, int ray,
                                           float& cx, float& cy, float& cz) {
    cx = fmaf(3.0f, rd[3 * ray + 0], ro[3 * ray + 0]);
    cy = fmaf(3.0f, rd[3 * ray + 1], ro[3 * ray + 1]);
    cz = fmaf(3.0f, rd[3 * ray + 2], ro[3 * ray + 2]);
}

// Monotone float <-> uint32 (order-preserving incl. +/-inf)
__device__ __forceinline__ unsigned f2sort(float f) {
    unsigned u = __float_as_uint(f);
    return ((int)u < 0) ? ~u : (u | 0x80000000u);
}
__device__ __forceinline__ float sort2f(unsigned s) {
    return (s & 0x80000000u) ? __uint_as_float(s ^ 0x80000000u)
                             : __uint_as_float(~s);
}

// Sorted top-10 insert (ascending); caller guarantees t < d[9].
__device__ __forceinline__ void insert10(float t, int i, float (&d)[TOPK], int (&id)[TOPK]) {
    int pos = TOPK - 1;
#pragma unroll
    for (int s = TOPK - 1; s > 0; --s) {
        if (t < d[s - 1]) { d[s] = d[s - 1]; id[s] = id[s - 1]; pos = s - 1; }
    }
    d[pos] = t; id[pos] = i;
}

// Warp-wide exact top-10 over per-lane sorted lists. Lane r<10 gets the r-th
// smallest unique key (sortable(t)<<32 | idx) in 'sel' — exact, stable.
__device__ __forceinline__ unsigned long long warp_select10(const float (&d)[TOPK],
                                                            const int (&id)[TOPK]) {
    int h = 0;
    unsigned long long cur =
        ((unsigned long long)f2sort(d[0]) << 32) | (unsigned)id[0];
    unsigned long long sel = 0xFFFFFFFFFFFFFFFFull;
#pragma unroll
    for (int r = 0; r < TOPK; ++r) {
        unsigned long long k = cur;
#pragma unroll
        for (int off = 16; off > 0; off >>= 1) {
            unsigned long long o = __shfl_xor_sync(0xFFFFFFFFu, k, off);
            k = o < k ? o : k;
        }
        if ((threadIdx.x & 31) == r) sel = k;
        if (cur == k) {
            ++h;
            cur = (h < TOPK)
                ? (((unsigned long long)f2sort(d[h]) << 32) | (unsigned)id[h])
                : 0xFFFFFFFFFFFFFFFFull;
        }
    }
    return sel;
}

// Warp epilogue: lanes 0..9 hold selected keys; writes out[ray].
__device__ __forceinline__ void epilogue(unsigned long long sel, int lane, float c2,
                                         const float* __restrict__ features_dc,
                                         const float* __restrict__ opacity,
                                         float* __restrict__ out, int ray) {
    float w = 0.f, wr = 0.f, wg = 0.f, wb = 0.f;
    if (lane < TOPK) {
        const int   k    = (int)(unsigned)sel;
        const float tv   = sort2f((unsigned)(sel >> 32));
        const float sq   = fmaxf(tv + c2, 0.0f);
        const float dist = sqrtf(sq);
        const float op   = 1.0f / (1.0f + expf(-opacity[k]));
        w  = expf(-0.1f * dist) * op;
        wr = w * (1.0f / (1.0f + expf(-features_dc[3 * k + 0])));
        wg = w * (1.0f / (1.0f + expf(-features_dc[3 * k + 1])));
        wb = w * (1.0f / (1.0f + expf(-features_dc[3 * k + 2])));
    }
#pragma unroll
    for (int off = 16; off > 0; off >>= 1) {
        w  += __shfl_xor_sync(0xFFFFFFFFu, w,  off);
        wr += __shfl_xor_sync(0xFFFFFFFFu, wr, off);
        wg += __shfl_xor_sync(0xFFFFFFFFu, wg, off);
        wb += __shfl_xor_sync(0xFFFFFFFFu, wb, off);
    }
    if (lane == 0) {
        const float inv = 1.0f / (w + 1e-8f);
        out[3 * ray + 0] = wr * inv;
        out[3 * ray + 1] = wg * inv;
        out[3 * ray + 2] = wb * inv;
    }
}

// ---------------------------------------------------------------------------
// 0. init: zero the two counters (graph replays need a clean slate)
// ---------------------------------------------------------------------------
__global__ void init_kernel() {
    if (threadIdx.x == 0) { g_ns = 0; g_over_cnt = 0; }
}

// ---------------------------------------------------------------------------
// 1. build: append shell points (w >= WCUT) with warp-aggregated atomics.
//    w chain: fmaf(x,x,fmaf(y,y,z*z)) — the canonical chain everywhere.
// ---------------------------------------------------------------------------
__global__ void __launch_bounds__(256)
build_kernel(const float* __restrict__ xyz) {
    const int i = blockIdx.x * blockDim.x + threadIdx.x;
    float x = 0.f, y = 0.f, z = 0.f, w = -1.0f;
    if (i < NPTS) {
        x = xyz[3 * i + 0]; y = xyz[3 * i + 1]; z = xyz[3 * i + 2];
        w = fmaf(x, x, fmaf(y, y, z * z));
    }
    const bool q = (w >= WCUT);
    const unsigned mask = __ballot_sync(0xFFFFFFFFu, q);
    if (mask == 0u) return;
    const int lane = threadIdx.x & 31;
    const int n = __popc(mask);
    const int leader = __ffs(mask) - 1;
    int base = 0;
    if (lane == leader) base = atomicAdd(&g_ns, n);
    base = __shfl_sync(0xFFFFFFFFu, base, leader);
    if (q) {
        const int pos = base + __popc(mask & ((1u << lane) - 1u));
        if (pos < SMAXN) {
            g_shell[pos] = make_float4(x, y, z, w);
            g_sidx[pos]  = i;
        }
    }
}

// ---------------------------------------------------------------------------
// 2. fused: warp per ray.
//    pass 1: lane-minima over the shell -> tau = 10th of 32 minima (sound).
//    check : rlo^2 (guarded) >= WCUT proves all true 10-NN are in the shell.
//    pass 2: tau-gated exact scan of the shell -> warp top-10 -> epilogue.
// ---------------------------------------------------------------------------
__global__ void __launch_bounds__(FWARPS * 32)
fused_kernel(const float* __restrict__ rays_o, const float* __restrict__ rays_d,
             const float* __restrict__ features_dc, const float* __restrict__ opacity,
             float* __restrict__ out) {
    const int warp = threadIdx.x >> 5;
    const int lane = threadIdx.x & 31;
    const int ray  = blockIdx.x * FWARPS + warp;

    const int  ns_raw   = g_ns;
    const int  ns       = ns_raw < SMAXN ? ns_raw : SMAXN;
    const bool shell_ok = (ns_raw <= SMAXN);

    float cx, cy, cz;
    ray_center(rays_o, rays_d, ray, cx, cy, cz);
    const float mx = -2.0f * cx, my = -2.0f * cy, mz = -2.0f * cz;
    const float c2 = fmaf(cx, cx, fmaf(cy, cy, cz * cz));

    // --- pass 1: per-lane min over lane-strided shell ---
    float amin = CUDART_INF_F;
#pragma unroll 4
    for (int i = lane; i < ns; i += 32) {
        float4 p = g_shell[i];
        float t = fmaf(p.x, mx, fmaf(p.y, my, fmaf(p.z, mz, p.w)));
        amin = fminf(amin, t);
    }
    // tau = 10th smallest of the 32 lane-minima (duplicate pops only loosen tau)
    float v = amin, tenth = CUDART_INF_F;
#pragma unroll
    for (int r = 0; r < TOPK; ++r) {
        float m = v;
#pragma unroll
        for (int off = 16; off > 0; off >>= 1)
            m = fminf(m, __shfl_xor_sync(0xFFFFFFFFu, m, off));
        if (r == TOPK - 1) tenth = m;
        if (v == m) v = CUDART_INF_F;
    }
    const float tau = bump_up(tenth);

    // --- radius proof: every point with t < tau has |p| >= |c| - d_tau ---
    const float cnorm = sqrtf(c2);
    const float dtau  = sqrtf(fmaxf(c2 + tau, 0.0f));
    const float rlo   = cnorm - dtau;
    const float rlosq = (rlo > 0.0f) ? rlo * rlo * (1.0f - 1e-4f) - 1e-7f : -1.0f;

    if (!shell_ok || !(rlosq >= WCUT)) {
        if (lane == 0) {
            int s = atomicAdd(&g_over_cnt, 1);
            g_over_ray[s] = ray;
            g_over_tau[s] = tau;
        }
        return;
    }

    // --- pass 2: gated exact scan (shell provably contains the true 10-NN) ---
    float d[TOPK];
    int   id[TOPK];
#pragma unroll
    for (int j = 0; j < TOPK; ++j) { d[j] = CUDART_INF_F; id[j] = 0; }

#pragma unroll 4
    for (int i = lane; i < ns; i += 32) {
        float4 p = g_shell[i];
        float t = fmaf(p.x, mx, fmaf(p.y, my, fmaf(p.z, mz, p.w)));
        if (t < tau) {
            if (t < d[TOPK - 1]) insert10(t, g_sidx[i], d, id);
        }
    }

    unsigned long long sel = warp_select10(d, id);
    epilogue(sel, lane, c2, features_dc, opacity, out, ray);
}

// ---------------------------------------------------------------------------
// 3. overflow: block per deferred ray (grid-strided over 512 blocks, so even
//    a pathological all-defer regime stays fully parallel across the chip).
//    Full brute-force scan gated by the stored (sound) tau; identical chains.
// ---------------------------------------------------------------------------
__global__ void __launch_bounds__(256)
overflow_kernel(const float* __restrict__ xyz,
                const float* __restrict__ rays_o, const float* __restrict__ rays_d,
                const float* __restrict__ features_dc, const float* __restrict__ opacity,
                float* __restrict__ out) {
    __shared__ unsigned long long s_keys[8 * TOPK];
    const int warp  = threadIdx.x >> 5;
    const int lane  = threadIdx.x & 31;
    const int nover = g_over_cnt;

    for (int slot = blockIdx.x; slot < nover; slot += gridDim.x) {
        const int   ray = g_over_ray[slot];
        const float tau = g_over_tau[slot];

        float cx, cy, cz;
        ray_center(rays_o, rays_d, ray, cx, cy, cz);
        const float mx = -2.0f * cx, my = -2.0f * cy, mz = -2.0f * cz;
        const float c2 = fmaf(cx, cx, fmaf(cy, cy, cz * cz));

        float d[TOPK];
        int   id[TOPK];
#pragma unroll
        for (int j = 0; j < TOPK; ++j) { d[j] = CUDART_INF_F; id[j] = 0; }

        for (int i = threadIdx.x; i < NPTS; i += 256) {
            float x = xyz[3 * i + 0], y = xyz[3 * i + 1], z = xyz[3 * i + 2];
            float w = fmaf(x, x, fmaf(y, y, z * z));
            float t = fmaf(x, mx, fmaf(y, my, fmaf(z, mz, w)));
            if (t < tau && t < d[TOPK - 1]) insert10(t, i, d, id);
        }

        unsigned long long sel = warp_select10(d, id);
        if (lane < TOPK) s_keys[warp * TOPK + lane] = sel;
        __syncthreads();

        if (warp == 0) {
            unsigned long long loc[3];
#pragma unroll
            for (int j = 0; j < 3; ++j) {
                int p = lane * 3 + j;
                loc[j] = (p < 8 * TOPK) ? s_keys[p] : 0xFFFFFFFFFFFFFFFFull;
            }
            if (loc[1] < loc[0]) { unsigned long long t0 = loc[0]; loc[0] = loc[1]; loc[1] = t0; }
            if (loc[2] < loc[1]) { unsigned long long t0 = loc[1]; loc[1] = loc[2]; loc[2] = t0; }
            if (loc[1] < loc[0]) { unsigned long long t0 = loc[0]; loc[0] = loc[1]; loc[1] = t0; }

            int h = 0;
            unsigned long long cur = loc[0];
            unsigned long long sel2 = 0xFFFFFFFFFFFFFFFFull;
#pragma unroll
            for (int r = 0; r < TOPK; ++r) {
                unsigned long long k = cur;
#pragma unroll
                for (int off = 16; off > 0; off >>= 1) {
                    unsigned long long o = __shfl_xor_sync(0xFFFFFFFFu, k, off);
                    k = o < k ? o : k;
                }
                if (lane == r) sel2 = k;
                if (cur == k) {
                    ++h;
                    cur = (h < 3) ? loc[h] : 0xFFFFFFFFFFFFFFFFull;
                }
            }
            epilogue(sel2, lane, c2, features_dc, opacity, out, ray);
        }
        __syncthreads();
    }
}

// ---------------------------------------------------------------------------
// Launch
// ---------------------------------------------------------------------------
extern "C" void kernel_launch(void* const* d_in, const int* in_sizes, int n_in,
                              void* d_out, int out_size) {
    const float* rays_o      = (const float*)d_in[0];
    const float* rays_d      = (const float*)d_in[1];
    const float* xyz         = (const float*)d_in[2];
    const float* features_dc = (const float*)d_in[3];
    const float* opacity     = (const float*)d_in[4];
    float* out = (float*)d_out;

    init_kernel<<<1, 32>>>();
    build_kernel<<<(NPTS + 255) / 256, 256>>>(xyz);
    fused_kernel<<<BATCH / FWARPS, FWARPS * 32>>>(rays_o, rays_d, features_dc, opacity, out);
    overflow_kernel<<<512, 256>>>(xyz, rays_o, rays_d, features_dc, opacity, out);
}

// round 11
// speedup vs baseline: 3.7548x; 3.7548x over previous
#include <cuda_runtime.h>
#include <math_constants.h>

// Problem constants
#define NPTS   100000
#define BATCH  4096
#define TOPK   10

// Shell: points with |p|^2 >= WCUT. Affects SPEED only; correctness is
// guarded by the per-ray radius proof and the overflow path.
#define WCUT   0.0992f
#define SMAXN  16384
#define FWARPS 8

// Overflow slicing: each deferred ray's 100k-point scan is split across
// NSLICE blocks so a single deferred ray costs ~µs, not ~200µs (R10 lesson).
#define NSLICE      64
#define SLICE_PTS   1563            // ceil(NPTS / NSLICE); 64*1563 = 100032
#define OVR_BLOCKS  4096

// ---------------------------------------------------------------------------
// Device scratch (static; no runtime allocation)
// ---------------------------------------------------------------------------
__device__ float4 g_shell[SMAXN];     // (x, y, z, |p|^2), unordered
__device__ int    g_sidx[SMAXN];      // original point index
__device__ int    g_ns;               // shell count (logical)
__device__ int    g_over_cnt;         // deferred ray count
__device__ int    g_over_ray[BATCH];
__device__ float  g_over_tau[BATCH];
__device__ unsigned long long g_part[BATCH * NSLICE * TOPK];  // per-slice top-10 keys

// ---------------------------------------------------------------------------
// Helpers
// ---------------------------------------------------------------------------
__device__ __forceinline__ float bump_up(float x) {
    unsigned u = __float_as_uint(x);
    if (x > 0.0f)      { u += 8; }
    else if (x < 0.0f) { if ((u & 0x7FFFFFFFu) <= 8u) return 1e-30f; u -= 8; }
    else               { return 1e-30f; }
    return __uint_as_float(u);
}

__device__ __forceinline__ void ray_center(const float* ro, const float* rd, int ray,
                                           float& cx, float& cy, float& cz) {
    cx = fmaf(3.0f, rd[3 * ray + 0], ro[3 * ray + 0]);
    cy = fmaf(3.0f, rd[3 * ray + 1], ro[3 * ray + 1]);
    cz = fmaf(3.0f, rd[3 * ray + 2], ro[3 * ray + 2]);
}

// Monotone float <-> uint32 (order-preserving incl. +/-inf)
__device__ __forceinline__ unsigned f2sort(float f) {
    unsigned u = __float_as_uint(f);
    return ((int)u < 0) ? ~u : (u | 0x80000000u);
}
__device__ __forceinline__ float sort2f(unsigned s) {
    return (s & 0x80000000u) ? __uint_as_float(s ^ 0x80000000u)
                             : __uint_as_float(~s);
}

// Sorted top-10 insert (ascending); caller guarantees t < d[9].
__device__ __forceinline__ void insert10(float t, int i, float (&d)[TOPK], int (&id)[TOPK]) {
    int pos = TOPK - 1;
#pragma unroll
    for (int s = TOPK - 1; s > 0; --s) {
        if (t < d[s - 1]) { d[s] = d[s - 1]; id[s] = id[s - 1]; pos = s - 1; }
    }
    d[pos] = t; id[pos] = i;
}

// Sorted top-10 insert for u64 keys (ascending); caller guarantees k < dk[9].
__device__ __forceinline__ void insert10_u64(unsigned long long k,
                                             unsigned long long (&dk)[TOPK]) {
    int pos = TOPK - 1;
#pragma unroll
    for (int s = TOPK - 1; s > 0; --s) {
        if (k < dk[s - 1]) { dk[s] = dk[s - 1]; pos = s - 1; }
    }
    dk[pos] = k;
}

// Warp-wide exact top-10 over per-lane sorted (d, id) lists. Lane r<10 gets
// the r-th smallest unique key (f2sort(t)<<32 | idx) — exact, stable.
__device__ __forceinline__ unsigned long long warp_select10(const float (&d)[TOPK],
                                                            const int (&id)[TOPK]) {
    int h = 0;
    unsigned long long cur =
        ((unsigned long long)f2sort(d[0]) << 32) | (unsigned)id[0];
    unsigned long long sel = 0xFFFFFFFFFFFFFFFFull;
#pragma unroll
    for (int r = 0; r < TOPK; ++r) {
        unsigned long long k = cur;
#pragma unroll
        for (int off = 16; off > 0; off >>= 1) {
            unsigned long long o = __shfl_xor_sync(0xFFFFFFFFu, k, off);
            k = o < k ? o : k;
        }
        if ((threadIdx.x & 31) == r) sel = k;
        if (cur == k) {
            ++h;
            cur = (h < TOPK)
                ? (((unsigned long long)f2sort(d[h]) << 32) | (unsigned)id[h])
                : 0xFFFFFFFFFFFFFFFFull;
        }
    }
    return sel;
}

// Same, but over per-lane sorted u64 key lists.
__device__ __forceinline__ unsigned long long warp_select10_u64(
        const unsigned long long (&dk)[TOPK]) {
    int h = 0;
    unsigned long long cur = dk[0];
    unsigned long long sel = 0xFFFFFFFFFFFFFFFFull;
#pragma unroll
    for (int r = 0; r < TOPK; ++r) {
        unsigned long long k = cur;
#pragma unroll
        for (int off = 16; off > 0; off >>= 1) {
            unsigned long long o = __shfl_xor_sync(0xFFFFFFFFu, k, off);
            k = o < k ? o : k;
        }
        if ((threadIdx.x & 31) == r) sel = k;
        if (cur == k) {
            ++h;
            cur = (h < TOPK) ? dk[h] : 0xFFFFFFFFFFFFFFFFull;
        }
    }
    return sel;
}

// Warp epilogue: lanes 0..9 hold selected keys; writes out[ray].
__device__ __forceinline__ void epilogue(unsigned long long sel, int lane, float c2,
                                         const float* __restrict__ features_dc,
                                         const float* __restrict__ opacity,
                                         float* __restrict__ out, int ray) {
    float w = 0.f, wr = 0.f, wg = 0.f, wb = 0.f;
    if (lane < TOPK) {
        const int   k    = (int)(unsigned)sel;
        const float tv   = sort2f((unsigned)(sel >> 32));
        const float sq   = fmaxf(tv + c2, 0.0f);
        const float dist = sqrtf(sq);
        const float op   = 1.0f / (1.0f + expf(-opacity[k]));
        w  = expf(-0.1f * dist) * op;
        wr = w * (1.0f / (1.0f + expf(-features_dc[3 * k + 0])));
        wg = w * (1.0f / (1.0f + expf(-features_dc[3 * k + 1])));
        wb = w * (1.0f / (1.0f + expf(-features_dc[3 * k + 2])));
    }
#pragma unroll
    for (int off = 16; off > 0; off >>= 1) {
        w  += __shfl_xor_sync(0xFFFFFFFFu, w,  off);
        wr += __shfl_xor_sync(0xFFFFFFFFu, wr, off);
        wg += __shfl_xor_sync(0xFFFFFFFFu, wg, off);
        wb += __shfl_xor_sync(0xFFFFFFFFu, wb, off);
    }
    if (lane == 0) {
        const float inv = 1.0f / (w + 1e-8f);
        out[3 * ray + 0] = wr * inv;
        out[3 * ray + 1] = wg * inv;
        out[3 * ray + 2] = wb * inv;
    }
}

// ---------------------------------------------------------------------------
// 0. init: zero counters (each graph replay needs a clean slate)
// ---------------------------------------------------------------------------
__global__ void init_kernel() {
    if (threadIdx.x == 0) { g_ns = 0; g_over_cnt = 0; }
}

// ---------------------------------------------------------------------------
// 1. build: append shell points (w >= WCUT) with warp-aggregated atomics.
// ---------------------------------------------------------------------------
__global__ void __launch_bounds__(256)
build_kernel(const float* __restrict__ xyz) {
    const int i = blockIdx.x * blockDim.x + threadIdx.x;
    float x = 0.f, y = 0.f, z = 0.f, w = -1.0f;
    if (i < NPTS) {
        x = xyz[3 * i + 0]; y = xyz[3 * i + 1]; z = xyz[3 * i + 2];
        w = fmaf(x, x, fmaf(y, y, z * z));
    }
    const bool q = (w >= WCUT);
    const unsigned mask = __ballot_sync(0xFFFFFFFFu, q);
    if (mask == 0u) return;
    const int lane = threadIdx.x & 31;
    const int n = __popc(mask);
    const int leader = __ffs(mask) - 1;
    int base = 0;
    if (lane == leader) base = atomicAdd(&g_ns, n);
    base = __shfl_sync(0xFFFFFFFFu, base, leader);
    if (q) {
        const int pos = base + __popc(mask & ((1u << lane) - 1u));
        if (pos < SMAXN) {
            g_shell[pos] = make_float4(x, y, z, w);
            g_sidx[pos]  = i;
        }
    }
}

// ---------------------------------------------------------------------------
// 2. fused: warp per ray. tau from shell -> radius proof -> gated exact scan.
//    Rays failing the proof (interior rays) defer to the sliced overflow.
// ---------------------------------------------------------------------------
__global__ void __launch_bounds__(FWARPS * 32)
fused_kernel(const float* __restrict__ rays_o, const float* __restrict__ rays_d,
             const float* __restrict__ features_dc, const float* __restrict__ opacity,
             float* __restrict__ out) {
    const int warp = threadIdx.x >> 5;
    const int lane = threadIdx.x & 31;
    const int ray  = blockIdx.x * FWARPS + warp;

    const int  ns_raw   = g_ns;
    const int  ns       = ns_raw < SMAXN ? ns_raw : SMAXN;
    const bool shell_ok = (ns_raw <= SMAXN);

    float cx, cy, cz;
    ray_center(rays_o, rays_d, ray, cx, cy, cz);
    const float mx = -2.0f * cx, my = -2.0f * cy, mz = -2.0f * cz;
    const float c2 = fmaf(cx, cx, fmaf(cy, cy, cz * cz));

    // pass 1: per-lane min over lane-strided shell
    float amin = CUDART_INF_F;
#pragma unroll 4
    for (int i = lane; i < ns; i += 32) {
        float4 p = g_shell[i];
        float t = fmaf(p.x, mx, fmaf(p.y, my, fmaf(p.z, mz, p.w)));
        amin = fminf(amin, t);
    }
    // tau = 10th smallest of the 32 lane-minima (subset 10th >= true 10th: sound)
    float v = amin, tenth = CUDART_INF_F;
#pragma unroll
    for (int r = 0; r < TOPK; ++r) {
        float m = v;
#pragma unroll
        for (int off = 16; off > 0; off >>= 1)
            m = fminf(m, __shfl_xor_sync(0xFFFFFFFFu, m, off));
        if (r == TOPK - 1) tenth = m;
        if (v == m) v = CUDART_INF_F;
    }
    const float tau = bump_up(tenth);

    // radius proof: any point with t < tau has |p| >= |c| - d_tau
    const float cnorm = sqrtf(c2);
    const float dtau  = sqrtf(fmaxf(c2 + tau, 0.0f));
    const float rlo   = cnorm - dtau;
    const float rlosq = (rlo > 0.0f) ? rlo * rlo * (1.0f - 1e-4f) - 1e-7f : -1.0f;

    if (!shell_ok || !(rlosq >= WCUT)) {
        if (lane == 0) {
            int s = atomicAdd(&g_over_cnt, 1);
            g_over_ray[s] = ray;
            g_over_tau[s] = tau;
        }
        return;
    }

    // pass 2: gated exact scan (shell provably contains the true 10-NN)
    float d[TOPK];
    int   id[TOPK];
#pragma unroll
    for (int j = 0; j < TOPK; ++j) { d[j] = CUDART_INF_F; id[j] = 0; }

#pragma unroll 4
    for (int i = lane; i < ns; i += 32) {
        float4 p = g_shell[i];
        float t = fmaf(p.x, mx, fmaf(p.y, my, fmaf(p.z, mz, p.w)));
        if (t < tau) {
            if (t < d[TOPK - 1]) insert10(t, g_sidx[i], d, id);
        }
    }

    unsigned long long sel = warp_select10(d, id);
    epilogue(sel, lane, c2, features_dc, opacity, out, ray);
}

// ---------------------------------------------------------------------------
// 3a. overflow stage A: block per (deferred ray, point slice), grid-strided.
//     Batched predicated loads (MLP~21) -> per-thread top-10 -> warp select
//     -> 80-key block merge -> slice top-10 keys to g_part.
// ---------------------------------------------------------------------------
__global__ void __launch_bounds__(256)
over_partial_kernel(const float* __restrict__ xyz,
                    const float* __restrict__ rays_o, const float* __restrict__ rays_d) {
    __shared__ unsigned long long s_keys[8 * TOPK];
    const int warp  = threadIdx.x >> 5;
    const int lane  = threadIdx.x & 31;
    const int nover = g_over_cnt;
    const int total = nover * NSLICE;

    for (int unit = blockIdx.x; unit < total; unit += gridDim.x) {
        const int slot  = unit >> 6;           // / NSLICE
        const int slice = unit & (NSLICE - 1);
        const int   ray = g_over_ray[slot];
        const float tau = g_over_tau[slot];

        float cx, cy, cz;
        ray_center(rays_o, rays_d, ray, cx, cy, cz);
        const float mx = -2.0f * cx, my = -2.0f * cy, mz = -2.0f * cz;

        const int i0 = slice * SLICE_PTS;
        const int i1 = (i0 + SLICE_PTS < NPTS) ? i0 + SLICE_PTS : NPTS;

        // batched predicated loads: up to 7 points per thread, all in flight
        float px[7], py[7], pz[7];
        int   pi[7];
#pragma unroll
        for (int j = 0; j < 7; ++j) {
            const int i = i0 + threadIdx.x + j * 256;
            pi[j] = (i < i1) ? i : -1;
            if (pi[j] >= 0) {
                px[j] = xyz[3 * i + 0];
                py[j] = xyz[3 * i + 1];
                pz[j] = xyz[3 * i + 2];
            }
        }

        float d[TOPK];
        int   id[TOPK];
#pragma unroll
        for (int j = 0; j < TOPK; ++j) { d[j] = CUDART_INF_F; id[j] = 0; }

#pragma unroll
        for (int j = 0; j < 7; ++j) {
            if (pi[j] >= 0) {
                // canonical chains (bit-identical to build/fused)
                float w = fmaf(px[j], px[j], fmaf(py[j], py[j], pz[j] * pz[j]));
                float t = fmaf(px[j], mx, fmaf(py[j], my, fmaf(pz[j], mz, w)));
                if (t < tau && t < d[TOPK - 1]) insert10(t, pi[j], d, id);
            }
        }

        unsigned long long sel = warp_select10(d, id);
        if (lane < TOPK) s_keys[warp * TOPK + lane] = sel;
        __syncthreads();

        if (warp == 0) {
            unsigned long long loc[3];
#pragma unroll
            for (int j = 0; j < 3; ++j) {
                int p = lane * 3 + j;
                loc[j] = (p < 8 * TOPK) ? s_keys[p] : 0xFFFFFFFFFFFFFFFFull;
            }
            if (loc[1] < loc[0]) { unsigned long long t0 = loc[0]; loc[0] = loc[1]; loc[1] = t0; }
            if (loc[2] < loc[1]) { unsigned long long t0 = loc[1]; loc[1] = loc[2]; loc[2] = t0; }
            if (loc[1] < loc[0]) { unsigned long long t0 = loc[0]; loc[0] = loc[1]; loc[1] = t0; }

            int h = 0;
            unsigned long long cur = loc[0];
            unsigned long long sel2 = 0xFFFFFFFFFFFFFFFFull;
#pragma unroll
            for (int r = 0; r < TOPK; ++r) {
                unsigned long long k = cur;
#pragma unroll
                for (int off = 16; off > 0; off >>= 1) {
                    unsigned long long o = __shfl_xor_sync(0xFFFFFFFFu, k, off);
                    k = o < k ? o : k;
                }
                if (lane == r) sel2 = k;
                if (cur == k) {
                    ++h;
                    cur = (h < 3) ? loc[h] : 0xFFFFFFFFFFFFFFFFull;
                }
            }
            if (lane < TOPK) g_part[unit * TOPK + lane] = sel2;
        }
        __syncthreads();
    }
}

// ---------------------------------------------------------------------------
// 3b. overflow stage B: warp per deferred ray. Merge 64 slices x 10 keys
//     (20 per lane, sorted insert) -> exact warp top-10 -> epilogue.
// ---------------------------------------------------------------------------
__global__ void __launch_bounds__(256)
over_merge_kernel(const float* __restrict__ rays_o, const float* __restrict__ rays_d,
                  const float* __restrict__ features_dc, const float* __restrict__ opacity,
                  float* __restrict__ out) {
    const int warp  = threadIdx.x >> 5;
    const int lane  = threadIdx.x & 31;
    const int gw    = blockIdx.x * 8 + warp;
    const int nwarp = gridDim.x * 8;
    const int nover = g_over_cnt;

    for (int slot = gw; slot < nover; slot += nwarp) {
        const int ray = g_over_ray[slot];

        unsigned long long dk[TOPK];
#pragma unroll
        for (int j = 0; j < TOPK; ++j) dk[j] = 0xFFFFFFFFFFFFFFFFull;

        const unsigned long long* __restrict__ part = g_part + slot * (NSLICE * TOPK);
        // 640 keys total; lane takes 20 contiguous
#pragma unroll 4
        for (int j = 0; j < 20; ++j) {
            unsigned long long k = part[lane * 20 + j];
            if (k < dk[TOPK - 1]) insert10_u64(k, dk);
        }

        unsigned long long sel = warp_select10_u64(dk);

        float cx, cy, cz;
        ray_center(rays_o, rays_d, ray, cx, cy, cz);
        const float c2 = fmaf(cx, cx, fmaf(cy, cy, cz * cz));
        epilogue(sel, lane, c2, features_dc, opacity, out, ray);
    }
}

// ---------------------------------------------------------------------------
// Launch
// ---------------------------------------------------------------------------
extern "C" void kernel_launch(void* const* d_in, const int* in_sizes, int n_in,
                              void* d_out, int out_size) {
    const float* rays_o      = (const float*)d_in[0];
    const float* rays_d      = (const float*)d_in[1];
    const float* xyz         = (const float*)d_in[2];
    const float* features_dc = (const float*)d_in[3];
    const float* opacity     = (const float*)d_in[4];
    float* out = (float*)d_out;

    init_kernel<<<1, 32>>>();
    build_kernel<<<(NPTS + 255) / 256, 256>>>(xyz);
    fused_kernel<<<BATCH / FWARPS, FWARPS * 32>>>(rays_o, rays_d, features_dc, opacity, out);
    over_partial_kernel<<<OVR_BLOCKS, 256>>>(xyz, rays_o, rays_d);
    over_merge_kernel<<<512, 256>>>(rays_o, rays_d, features_dc, opacity, out);
}